// round 5
// baseline (speedup 1.0000x reference)
#include <cuda_runtime.h>
#include <math.h>

#define NN        21
#define NN2       441
#define NFEAT     128
#define FC1_OUT   512
#define FC2_OUT   512
#define FC3_OUT   256
#define FC1_K     441
#define FC2_K     512
#define FC3_K     512

#define NBLK      41           // b0 GCN-final | b1-16 FC1 | b17-32 FC2 | b33-40 FC3(+GCN rows)
#define NTHREADS  512

// ---- packed handoff slots: u64 = {hi: gen(1 when valid), lo: f32 bits} ----
// one copy per consumer block; consumer resets to 0 after reading.
// zero-initialized at module load; resets preserve the invariant across replays.
__device__ unsigned long long g_pp[448];          // p = (X@W1)@W2 rows  -> block0
__device__ unsigned long long g_vp[16][448];      // v  -> 16 FC1 blocks
__device__ unsigned long long g_x1p[16][512];     // x1 -> 16 FC2 blocks
__device__ unsigned long long g_x2p[8][512];      // x2 -> 8 FC3 blocks

__device__ __forceinline__ unsigned long long ld_rlx(const unsigned long long* p) {
    unsigned long long v;
    asm volatile("ld.relaxed.gpu.global.u64 %0, [%1];" : "=l"(v) : "l"(p) : "memory");
    return v;
}
__device__ __forceinline__ void st_rlx(unsigned long long* p, unsigned long long v) {
    asm volatile("st.relaxed.gpu.global.u64 [%0], %1;" :: "l"(p), "l"(v) : "memory");
}
__device__ __forceinline__ unsigned long long pack1(float f) {
    return (1ULL << 32) | (unsigned long long)__float_as_uint(f);
}
__device__ __forceinline__ float poll_take(unsigned long long* slot) {
    unsigned long long u;
    do { u = ld_rlx(slot); } while ((u >> 32) == 0ULL);
    st_rlx(slot, 0ULL);
    return __uint_as_float((unsigned)u);
}

// dynamic smem: ws [0,65536) | red [65536,67584) | scratch [67584, +16KB)
#define SMEM_BYTES 83968

__global__ void __launch_bounds__(NTHREADS, 1)
fused_net_kernel(const float* __restrict__ state,
                 const int*   __restrict__ edge_index, int n_edges,
                 const float* __restrict__ W1,  const float* __restrict__ b1,
                 const float* __restrict__ W2,  const float* __restrict__ b2,
                 const float* __restrict__ Wf1, const float* __restrict__ bf1,
                 const float* __restrict__ Wf2, const float* __restrict__ bf2,
                 const float* __restrict__ Wf3, const float* __restrict__ bf3,
                 float* __restrict__ out)
{
    extern __shared__ char smem[];
    float* ws      = (float*)smem;                 // [K x 32] FC weights
    float* red     = (float*)(smem + 65536);       // [512]
    float* scratch = (float*)(smem + 67584);
    const int t = threadIdx.x;
    const int b = blockIdx.x;

    if (b == 0) {
        // ============ block0: adjacency -> A_norm -> A2, r, c; then v =====
        float* sA   = scratch;            // 441
        float* sA2  = sA   + 448;         // 441
        float* sP   = sA2  + 448;         // 441 (polled p)
        float* sW2  = sP   + 448;         // 441
        float* sb1  = sW2  + 448;         // 21
        float* sb2  = sb1  + 32;          // 21
        float* sr   = sb2  + 32;          // 21
        float* sc   = sr   + 32;          // 21
        float* sdinv= sc   + 32;          // 21

        if (t < NN2) { sA[t] = 0.f; sW2[t] = W2[t]; }
        if (t < NN)  { sb1[t] = b1[t]; sb2[t] = b2[t]; }
        __syncthreads();

        for (int e = t; e < n_edges; e += NTHREADS) {
            int r = edge_index[e];
            int c = edge_index[n_edges + e];
            atomicAdd(&sA[r * NN + c], 1.0f);
        }
        __syncthreads();
        if (t < NN) sA[t * NN + t] += 1.0f;
        __syncthreads();
        if (t < NN) {
            float d = 0.f;
            #pragma unroll
            for (int i = 0; i < NN; i++) d += sA[i * NN + t];
            sdinv[t] = (d > 0.f) ? rsqrtf(d) : 0.f;
        }
        __syncthreads();
        if (t < NN2) {
            int i = t / NN, j = t % NN;
            sA[t] *= sdinv[i] * sdinv[j];
        }
        __syncthreads();

        // A2 = A@A ; r = row sums of A ; c = b1^T @ W2   (all parallel)
        if (t < NN2) {
            int i = t / NN, j = t % NN;
            float a0 = 0.f, a1 = 0.f;
            #pragma unroll
            for (int k = 0; k < 20; k += 2) {
                a0 += sA[i * NN + k]     * sA[k * NN + j];
                a1 += sA[i * NN + k + 1] * sA[(k + 1) * NN + j];
            }
            a0 += sA[i * NN + 20] * sA[20 * NN + j];
            sA2[t] = a0 + a1;
        }
        if (t >= 448 && t < 448 + NN) {
            int i = t - 448;
            float s = 0.f;
            #pragma unroll
            for (int k = 0; k < NN; k++) s += sA[i * NN + k];
            sr[i] = s;
        }
        if (t >= 480 && t < 480 + NN) {
            int j = t - 480;
            float s = 0.f;
            #pragma unroll
            for (int k = 0; k < NN; k++) s += sb1[k] * sW2[k * NN + j];
            sc[j] = s;
        }
        __syncthreads();

        // poll p rows (produced by FC3 blocks)
        if (t < NN2) sP[t] = poll_take(&g_pp[t]);
        __syncthreads();

        // v = A2 @ p + r (x) c + b2 ; publish 16 copies
        if (t < NN2) {
            int i = t / NN, j = t % NN;
            float a0 = sr[i] * sc[j] + sb2[j];
            float a1 = 0.f;
            #pragma unroll
            for (int k = 0; k < 20; k += 2) {
                a0 += sA2[i * NN + k]     * sP[k * NN + j];
                a1 += sA2[i * NN + k + 1] * sP[(k + 1) * NN + j];
            }
            a0 += sA2[i * NN + 20] * sP[20 * NN + j];
            unsigned long long pk = pack1(a0 + a1);
            #pragma unroll
            for (int c2 = 0; c2 < 16; c2++) st_rlx(&g_vp[c2][t], pk);
        }
        return;
    }

    const int j  = t & 31;                        // lane
    const int kg = t >> 5;                        // warp

    if (b <= 16) {
        // ================= FC1: K=441, 32 outputs ==========================
        const int jt = b - 1;
        const float bias = (t < 32) ? __ldg(&bf1[jt * 32 + t]) : 0.f;
        {
            const float4* W4 = (const float4*)Wf1;
            float4* ws4 = (float4*)ws;
            for (int i = t; i < FC1_K * 8; i += NTHREADS) {
                int k = i >> 3, c = i & 7;
                ws4[k * 8 + c] = W4[k * (FC1_OUT / 4) + jt * 8 + c];
            }
        }
        const int k0   = kg * 28;
        const int klen = min(FC1_K - k0, 28);
        float xv = 0.f;
        if (j < klen) xv = poll_take(&g_vp[jt][k0 + j]);

        float a0 = 0.f, a1 = 0.f, a2 = 0.f, a3 = 0.f;
        int kk = 0;
        for (; kk + 4 <= klen; kk += 4) {
            a0 += __shfl_sync(0xffffffffu, xv, kk)     * ws[(k0 + kk)     * 32 + j];
            a1 += __shfl_sync(0xffffffffu, xv, kk + 1) * ws[(k0 + kk + 1) * 32 + j];
            a2 += __shfl_sync(0xffffffffu, xv, kk + 2) * ws[(k0 + kk + 2) * 32 + j];
            a3 += __shfl_sync(0xffffffffu, xv, kk + 3) * ws[(k0 + kk + 3) * 32 + j];
        }
        for (; kk < klen; kk++)
            a0 += __shfl_sync(0xffffffffu, xv, kk) * ws[(k0 + kk) * 32 + j];
        red[t] = (a0 + a1) + (a2 + a3);
        __syncthreads();
        if (t < 32) {
            float s0 = red[t]       + red[t + 32];
            float s1 = red[t + 64]  + red[t + 96];
            float s2 = red[t + 128] + red[t + 160];
            float s3 = red[t + 192] + red[t + 224];
            float s4 = red[t + 256] + red[t + 288];
            float s5 = red[t + 320] + red[t + 352];
            float s6 = red[t + 384] + red[t + 416];
            float s7 = red[t + 448] + red[t + 480];
            float s  = ((s0 + s1) + (s2 + s3)) + ((s4 + s5) + (s6 + s7));
            unsigned long long pk = pack1(fmaxf(s + bias, 0.f));
            #pragma unroll
            for (int c = 0; c < 16; c++) st_rlx(&g_x1p[c][jt * 32 + t], pk);
        }
        return;
    }

    if (b <= 32) {
        // ================= FC2: K=512, 32 outputs ==========================
        const int jt = b - 17;
        const float bias = (t < 32) ? __ldg(&bf2[jt * 32 + t]) : 0.f;
        {
            const float4* W4 = (const float4*)Wf2;
            float4* ws4 = (float4*)ws;
            for (int i = t; i < FC2_K * 8; i += NTHREADS) {
                int k = i >> 3, c = i & 7;
                ws4[k * 8 + c] = W4[k * (FC2_OUT / 4) + jt * 8 + c];
            }
        }
        const int k0 = kg * 32;
        float xv = poll_take(&g_x1p[jt][k0 + j]);

        float a0 = 0.f, a1 = 0.f, a2 = 0.f, a3 = 0.f;
        #pragma unroll
        for (int kk = 0; kk < 32; kk += 4) {
            a0 += __shfl_sync(0xffffffffu, xv, kk)     * ws[(k0 + kk)     * 32 + j];
            a1 += __shfl_sync(0xffffffffu, xv, kk + 1) * ws[(k0 + kk + 1) * 32 + j];
            a2 += __shfl_sync(0xffffffffu, xv, kk + 2) * ws[(k0 + kk + 2) * 32 + j];
            a3 += __shfl_sync(0xffffffffu, xv, kk + 3) * ws[(k0 + kk + 3) * 32 + j];
        }
        red[t] = (a0 + a1) + (a2 + a3);
        __syncthreads();
        if (t < 32) {
            float s0 = red[t]       + red[t + 32];
            float s1 = red[t + 64]  + red[t + 96];
            float s2 = red[t + 128] + red[t + 160];
            float s3 = red[t + 192] + red[t + 224];
            float s4 = red[t + 256] + red[t + 288];
            float s5 = red[t + 320] + red[t + 352];
            float s6 = red[t + 384] + red[t + 416];
            float s7 = red[t + 448] + red[t + 480];
            float s  = ((s0 + s1) + (s2 + s3)) + ((s4 + s5) + (s6 + s7));
            unsigned long long pk = pack1(fmaxf(s + bias, 0.f));
            #pragma unroll
            for (int c = 0; c < 8; c++) st_rlx(&g_x2p[c][jt * 32 + t], pk);
        }
        return;
    }

    // ================= FC3 blocks (b 33..40): GCN rows first ==============
    {
        const int g3 = b - 33;                    // 0..7

        if (g3 < 7) {
            // ---- compute p rows R0..R0+2 : p = (X@W1) @ W2 ----
            float* sXr  = scratch;            // 3*128
            float* sW1g = sXr  + 384;         // 2688
            float* sW2s = sW1g + 2688;        // 441
            float* sH   = sW2s + 448;         // 63
            float* pr   = sH   + 64;          // 504

            const int R0 = g3 * 3;
            {
                const float4* X4 = (const float4*)(state + R0 * NFEAT);
                float4* d4 = (float4*)sXr;
                if (t < 96) d4[t] = X4[t];
                const float4* W14 = (const float4*)W1;
                float4* w14 = (float4*)sW1g;
                for (int i = t; i < 672; i += NTHREADS) w14[i] = W14[i];
                if (t < NN2) sW2s[t] = W2[t];
            }
            __syncthreads();

            // h1 rows: 63 outputs x 8-way k-split (504 threads)
            if (t < 504) {
                int o  = t >> 3;              // 0..62
                int s  = t & 7;
                int ri = o / NN, jj = o % NN;
                int k0 = s * 16;
                float a0 = 0.f, a1 = 0.f, a2 = 0.f, a3 = 0.f;
                #pragma unroll
                for (int kk = 0; kk < 16; kk += 4) {
                    a0 += sXr[ri * NFEAT + k0 + kk]     * sW1g[(k0 + kk)     * NN + jj];
                    a1 += sXr[ri * NFEAT + k0 + kk + 1] * sW1g[(k0 + kk + 1) * NN + jj];
                    a2 += sXr[ri * NFEAT + k0 + kk + 2] * sW1g[(k0 + kk + 2) * NN + jj];
                    a3 += sXr[ri * NFEAT + k0 + kk + 3] * sW1g[(k0 + kk + 3) * NN + jj];
                }
                pr[t] = (a0 + a1) + (a2 + a3);
            }
            __syncthreads();
            if (t < 63) {
                float s0 = pr[t * 8]     + pr[t * 8 + 1];
                float s1 = pr[t * 8 + 2] + pr[t * 8 + 3];
                float s2 = pr[t * 8 + 4] + pr[t * 8 + 5];
                float s3 = pr[t * 8 + 6] + pr[t * 8 + 7];
                sH[t] = (s0 + s1) + (s2 + s3);
            }
            __syncthreads();
            if (t < 63) {
                int ri = t / NN, jj = t % NN;
                float a0 = 0.f, a1 = 0.f;
                #pragma unroll
                for (int k = 0; k < 20; k += 2) {
                    a0 += sH[ri * NN + k]     * sW2s[k * NN + jj];
                    a1 += sH[ri * NN + k + 1] * sW2s[(k + 1) * NN + jj];
                }
                a0 += sH[ri * NN + 20] * sW2s[20 * NN + jj];
                st_rlx(&g_pp[(R0 + ri) * NN + jj], pack1(a0 + a1));
            }
        }

        // ---- FC3 proper: preload weights, then consume x2 ----
        const float bias = (t < 32) ? __ldg(&bf3[g3 * 32 + t]) : 0.f;
        {
            const float4* W4 = (const float4*)Wf3;
            float4* ws4 = (float4*)ws;
            for (int i = t; i < FC3_K * 8; i += NTHREADS) {
                int k = i >> 3, c = i & 7;
                ws4[k * 8 + c] = W4[k * (FC3_OUT / 4) + g3 * 8 + c];
            }
        }
        const int k0 = kg * 32;
        float xv = poll_take(&g_x2p[g3][k0 + j]);

        float a0 = 0.f, a1 = 0.f, a2 = 0.f, a3 = 0.f;
        #pragma unroll
        for (int kk = 0; kk < 32; kk += 4) {
            a0 += __shfl_sync(0xffffffffu, xv, kk)     * ws[(k0 + kk)     * 32 + j];
            a1 += __shfl_sync(0xffffffffu, xv, kk + 1) * ws[(k0 + kk + 1) * 32 + j];
            a2 += __shfl_sync(0xffffffffu, xv, kk + 2) * ws[(k0 + kk + 2) * 32 + j];
            a3 += __shfl_sync(0xffffffffu, xv, kk + 3) * ws[(k0 + kk + 3) * 32 + j];
        }
        red[t] = (a0 + a1) + (a2 + a3);
        __syncthreads();
        if (t < 32) {
            float s0 = red[t]       + red[t + 32];
            float s1 = red[t + 64]  + red[t + 96];
            float s2 = red[t + 128] + red[t + 160];
            float s3 = red[t + 192] + red[t + 224];
            float s4 = red[t + 256] + red[t + 288];
            float s5 = red[t + 320] + red[t + 352];
            float s6 = red[t + 384] + red[t + 416];
            float s7 = red[t + 448] + red[t + 480];
            float s  = ((s0 + s1) + (s2 + s3)) + ((s4 + s5) + (s6 + s7));
            out[g3 * 32 + t] = fmaxf(s + bias, 0.f);
        }
    }
}

// ---------------------------------------------------------------------------
extern "C" void kernel_launch(void* const* d_in, const int* in_sizes, int n_in,
                              void* d_out, int out_size)
{
    const float* state = (const float*)d_in[0];
    const int*   edges = (const int*)  d_in[1];
    const int n_edges  = in_sizes[1] / 2;

    const float* W1  = (const float*)d_in[2];
    const float* b1  = (const float*)d_in[3];
    const float* W2  = (const float*)d_in[4];
    const float* b2  = (const float*)d_in[5];
    const float* Wf1 = (const float*)d_in[6];
    const float* bf1 = (const float*)d_in[7];
    const float* Wf2 = (const float*)d_in[8];
    const float* bf2 = (const float*)d_in[9];
    const float* Wf3 = (const float*)d_in[10];
    const float* bf3 = (const float*)d_in[11];
    float* out = (float*)d_out;

    static bool attr_set = false;
    if (!attr_set) {
        cudaFuncSetAttribute(fused_net_kernel,
                             cudaFuncAttributeMaxDynamicSharedMemorySize,
                             SMEM_BYTES);
        attr_set = true;
    }

    fused_net_kernel<<<NBLK, NTHREADS, SMEM_BYTES>>>(
        state, edges, n_edges, W1, b1, W2, b2,
        Wf1, bf1, Wf2, bf2, Wf3, bf3, out);
}

// round 6
// speedup vs baseline: 1.6169x; 1.6169x over previous
#include <cuda_runtime.h>
#include <math.h>

#define NN        21
#define NN2       441
#define NFEAT     128
#define FC1_OUT   512
#define FC2_OUT   512
#define FC3_OUT   256
#define FC1_K     441
#define FC2_K     512
#define FC3_K     512

#define NBLK      41           // b0 GCN-final | b1-16 FC1 | b17-32 FC2 | b33-40 FC3(+p rows)
#define NTHREADS  512

// ---- data arrays (plain) + monotonic per-tile flags (never reset) ----
__device__ float g_p[448];
__device__ float g_v[448];
__device__ float g_x1[512];
__device__ float g_x2[512];
__device__ unsigned g_fp[7 * 32];      // p rows from FC3 block g3 (g3<7)
__device__ unsigned g_fv[32];          // v ready
__device__ unsigned g_fx1[16 * 32];    // x1 tile
__device__ unsigned g_fx2[16 * 32];    // x2 tile

__device__ __forceinline__ unsigned ld_acq(unsigned* p) {
    unsigned v;
    asm volatile("ld.acquire.gpu.global.u32 %0, [%1];" : "=r"(v) : "l"(p) : "memory");
    return v;
}
__device__ __forceinline__ unsigned ld_plain(unsigned* p) {
    unsigned v;
    asm volatile("ld.global.cg.u32 %0, [%1];" : "=r"(v) : "l"(p) : "memory");
    return v;
}
__device__ __forceinline__ void publish(unsigned* p) {
    asm volatile("red.release.gpu.global.add.u32 [%0], 1;" :: "l"(p) : "memory");
}
__device__ __forceinline__ void wait_flag(unsigned* p, unsigned old) {
    while (ld_acq(p) == old) { }
}

__global__ void __launch_bounds__(NTHREADS, 1)
fused_net_kernel(const float* __restrict__ state,
                 const int*   __restrict__ edge_index, int n_edges,
                 const float* __restrict__ W1,  const float* __restrict__ b1,
                 const float* __restrict__ W2,  const float* __restrict__ b2,
                 const float* __restrict__ Wf1, const float* __restrict__ bf1,
                 const float* __restrict__ Wf2, const float* __restrict__ bf2,
                 const float* __restrict__ Wf3, const float* __restrict__ bf3,
                 float* __restrict__ out)
{
    __shared__ float sh[4608];         // 18 KB static scratch, carved per role
    const int t = threadIdx.x;
    const int b = blockIdx.x;
    const int j  = t & 31;
    const int kg = t >> 5;

    if (b == 0) {
        // ====== block0: adjacency -> A_norm -> A2, r, c; poll p; emit v ====
        float* sA    = sh;            // 441
        float* sA2   = sh + 448;      // 441
        float* sP    = sh + 896;      // 441
        float* sW2   = sh + 1344;     // 441
        float* sb1   = sh + 1792;     // 21
        float* sb2   = sh + 1824;     // 21
        float* sr    = sh + 1856;     // 21
        float* sc    = sh + 1888;     // 21
        float* sdinv = sh + 1920;     // 21
        unsigned* soldp = (unsigned*)(sh + 1952); // 7

        if (t < 7) soldp[t] = ld_plain(&g_fp[t * 32]);   // sample early
        if (t < NN2) { sA[t] = 0.f; sW2[t] = W2[t]; }
        if (t < NN)  { sb1[t] = b1[t]; sb2[t] = b2[t]; }
        __syncthreads();

        for (int e = t; e < n_edges; e += NTHREADS) {
            int r = edge_index[e];
            int c = edge_index[n_edges + e];
            atomicAdd(&sA[r * NN + c], 1.0f);
        }
        __syncthreads();
        if (t < NN) sA[t * NN + t] += 1.0f;
        __syncthreads();
        if (t < NN) {
            float d = 0.f;
            #pragma unroll
            for (int i = 0; i < NN; i++) d += sA[i * NN + t];
            sdinv[t] = (d > 0.f) ? rsqrtf(d) : 0.f;
        }
        __syncthreads();
        if (t < NN2) {
            int i = t / NN, jj = t % NN;
            sA[t] *= sdinv[i] * sdinv[jj];
        }
        __syncthreads();

        // A2 = A@A ; r = row sums of A ; c = b1^T @ W2 (parallel)
        if (t < NN2) {
            int i = t / NN, jj = t % NN;
            float a0 = 0.f, a1 = 0.f;
            #pragma unroll
            for (int k = 0; k < 20; k += 2) {
                a0 += sA[i * NN + k]     * sA[k * NN + jj];
                a1 += sA[i * NN + k + 1] * sA[(k + 1) * NN + jj];
            }
            a0 += sA[i * NN + 20] * sA[20 * NN + jj];
            sA2[t] = a0 + a1;
        }
        if (t >= 448 && t < 448 + NN) {
            int i = t - 448;
            float s = 0.f;
            #pragma unroll
            for (int k = 0; k < NN; k++) s += sA[i * NN + k];
            sr[i] = s;
        }
        if (t >= 480 && t < 480 + NN) {
            int jj = t - 480;
            float s = 0.f;
            #pragma unroll
            for (int k = 0; k < NN; k++) s += sb1[k] * sW2[k * NN + jj];
            sc[jj] = s;
        }
        __syncthreads();

        // wait for the 7 p-producer flags (coalesced: warp i spins one addr)
        if (kg < 7) wait_flag(&g_fp[kg * 32], soldp[kg]);
        __syncthreads();
        if (t < NN2) sP[t] = __ldcg(&g_p[t]);
        __syncthreads();

        if (t < NN2) {
            int i = t / NN, jj = t % NN;
            float a0 = sr[i] * sc[jj] + sb2[jj];
            float a1 = 0.f;
            #pragma unroll
            for (int k = 0; k < 20; k += 2) {
                a0 += sA2[i * NN + k]     * sP[k * NN + jj];
                a1 += sA2[i * NN + k + 1] * sP[(k + 1) * NN + jj];
            }
            a0 += sA2[i * NN + 20] * sP[20 * NN + jj];
            g_v[t] = a0 + a1;
        }
        __syncthreads();
        if (t == 0) { __threadfence(); publish(&g_fv[0]); }
        return;
    }

    float* red = sh;                               // [512] reduction buffer

    if (b <= 16) {
        // ============ FC1: K=441, 32 outputs, register weights ============
        const int jt = b - 1;
        const unsigned oldv = ld_plain(&g_fv[0]);  // sample first
        const float bias = (t < 32) ? __ldg(&bf1[jt * 32 + t]) : 0.f;
        const int k0 = kg * 28;
        float w[28];
        #pragma unroll
        for (int kk = 0; kk < 28; kk++) {
            int k = k0 + kk;
            w[kk] = (k < FC1_K) ? __ldg(&Wf1[k * FC1_OUT + jt * 32 + j]) : 0.f;
        }
        wait_flag(&g_fv[0], oldv);
        float xv = (j < 28) ? __ldcg(&g_v[k0 + j]) : 0.f;   // g_v padded to 448

        float a0 = 0.f, a1 = 0.f, a2 = 0.f, a3 = 0.f;
        #pragma unroll
        for (int kk = 0; kk < 28; kk += 4) {
            a0 += __shfl_sync(0xffffffffu, xv, kk)     * w[kk];
            a1 += __shfl_sync(0xffffffffu, xv, kk + 1) * w[kk + 1];
            a2 += __shfl_sync(0xffffffffu, xv, kk + 2) * w[kk + 2];
            a3 += __shfl_sync(0xffffffffu, xv, kk + 3) * w[kk + 3];
        }
        red[t] = (a0 + a1) + (a2 + a3);
        __syncthreads();
        if (t < 32) {
            float s0 = red[t]       + red[t + 32];
            float s1 = red[t + 64]  + red[t + 96];
            float s2 = red[t + 128] + red[t + 160];
            float s3 = red[t + 192] + red[t + 224];
            float s4 = red[t + 256] + red[t + 288];
            float s5 = red[t + 320] + red[t + 352];
            float s6 = red[t + 384] + red[t + 416];
            float s7 = red[t + 448] + red[t + 480];
            float s  = ((s0 + s1) + (s2 + s3)) + ((s4 + s5) + (s6 + s7));
            g_x1[jt * 32 + t] = fmaxf(s + bias, 0.f);
            __syncwarp();
            if (t == 0) { __threadfence(); publish(&g_fx1[jt * 32]); }
        }
        return;
    }

    if (b <= 32) {
        // ============ FC2: K=512, 32 outputs, register weights ============
        const int jt = b - 17;
        const unsigned oldf = ld_plain(&g_fx1[kg * 32]);   // per-warp tile
        const float bias = (t < 32) ? __ldg(&bf2[jt * 32 + t]) : 0.f;
        const int k0 = kg * 32;
        float w[32];
        #pragma unroll
        for (int kk = 0; kk < 32; kk++)
            w[kk] = __ldg(&Wf2[(k0 + kk) * FC2_OUT + jt * 32 + j]);
        wait_flag(&g_fx1[kg * 32], oldf);
        float xv = __ldcg(&g_x1[k0 + j]);

        float a0 = 0.f, a1 = 0.f, a2 = 0.f, a3 = 0.f;
        #pragma unroll
        for (int kk = 0; kk < 32; kk += 4) {
            a0 += __shfl_sync(0xffffffffu, xv, kk)     * w[kk];
            a1 += __shfl_sync(0xffffffffu, xv, kk + 1) * w[kk + 1];
            a2 += __shfl_sync(0xffffffffu, xv, kk + 2) * w[kk + 2];
            a3 += __shfl_sync(0xffffffffu, xv, kk + 3) * w[kk + 3];
        }
        red[t] = (a0 + a1) + (a2 + a3);
        __syncthreads();
        if (t < 32) {
            float s0 = red[t]       + red[t + 32];
            float s1 = red[t + 64]  + red[t + 96];
            float s2 = red[t + 128] + red[t + 160];
            float s3 = red[t + 192] + red[t + 224];
            float s4 = red[t + 256] + red[t + 288];
            float s5 = red[t + 320] + red[t + 352];
            float s6 = red[t + 384] + red[t + 416];
            float s7 = red[t + 448] + red[t + 480];
            float s  = ((s0 + s1) + (s2 + s3)) + ((s4 + s5) + (s6 + s7));
            g_x2[jt * 32 + t] = fmaxf(s + bias, 0.f);
            __syncwarp();
            if (t == 0) { __threadfence(); publish(&g_fx2[jt * 32]); }
        }
        return;
    }

    // ============ FC3 blocks (b 33..40): p rows first, then FC3 ===========
    {
        const int g3 = b - 33;                            // 0..7
        const unsigned oldf = ld_plain(&g_fx2[kg * 32]);  // sample FIRST

        if (g3 < 7) {
            // ---- p rows R0..R0+2 : p = (X@W1) @ W2 ----
            float* sXr  = sh;            // 384
            float* sW1g = sh + 384;      // 2688
            float* sW2s = sh + 3072;     // 441
            float* sH   = sh + 3520;     // 63
            float* pr   = sh + 3584;     // 504

            const int R0 = g3 * 3;
            {
                const float4* X4 = (const float4*)(state + R0 * NFEAT);
                float4* d4 = (float4*)sXr;
                if (t < 96) d4[t] = X4[t];
                const float4* W14 = (const float4*)W1;
                float4* w14 = (float4*)sW1g;
                for (int i = t; i < 672; i += NTHREADS) w14[i] = W14[i];
                if (t < NN2) sW2s[t] = W2[t];
            }
            __syncthreads();

            if (t < 504) {               // h1 rows: 63 outs x 8-way k-split
                int o  = t >> 3;
                int s  = t & 7;
                int ri = o / NN, jj = o % NN;
                int kk0 = s * 16;
                float a0 = 0.f, a1 = 0.f, a2 = 0.f, a3 = 0.f;
                #pragma unroll
                for (int kk = 0; kk < 16; kk += 4) {
                    a0 += sXr[ri * NFEAT + kk0 + kk]     * sW1g[(kk0 + kk)     * NN + jj];
                    a1 += sXr[ri * NFEAT + kk0 + kk + 1] * sW1g[(kk0 + kk + 1) * NN + jj];
                    a2 += sXr[ri * NFEAT + kk0 + kk + 2] * sW1g[(kk0 + kk + 2) * NN + jj];
                    a3 += sXr[ri * NFEAT + kk0 + kk + 3] * sW1g[(kk0 + kk + 3) * NN + jj];
                }
                pr[t] = (a0 + a1) + (a2 + a3);
            }
            __syncthreads();
            if (t < 63) {
                float s0 = pr[t * 8]     + pr[t * 8 + 1];
                float s1 = pr[t * 8 + 2] + pr[t * 8 + 3];
                float s2 = pr[t * 8 + 4] + pr[t * 8 + 5];
                float s3 = pr[t * 8 + 6] + pr[t * 8 + 7];
                sH[t] = (s0 + s1) + (s2 + s3);
            }
            __syncthreads();
            if (t < 63) {
                int ri = t / NN, jj = t % NN;
                float a0 = 0.f, a1 = 0.f;
                #pragma unroll
                for (int k = 0; k < 20; k += 2) {
                    a0 += sH[ri * NN + k]     * sW2s[k * NN + jj];
                    a1 += sH[ri * NN + k + 1] * sW2s[(k + 1) * NN + jj];
                }
                a0 += sH[ri * NN + 20] * sW2s[20 * NN + jj];
                g_p[(R0 + ri) * NN + jj] = a0 + a1;
            }
            __syncthreads();
            if (t == 0) { __threadfence(); publish(&g_fp[g3 * 32]); }
            __syncthreads();           // scratch free before red reuse
        }

        // ---- FC3 proper: register weights, consume x2 ----
        const float bias = (t < 32) ? __ldg(&bf3[g3 * 32 + t]) : 0.f;
        const int k0 = kg * 32;
        float w[32];
        #pragma unroll
        for (int kk = 0; kk < 32; kk++)
            w[kk] = __ldg(&Wf3[(k0 + kk) * FC3_OUT + g3 * 32 + j]);
        wait_flag(&g_fx2[kg * 32], oldf);
        float xv = __ldcg(&g_x2[k0 + j]);

        float a0 = 0.f, a1 = 0.f, a2 = 0.f, a3 = 0.f;
        #pragma unroll
        for (int kk = 0; kk < 32; kk += 4) {
            a0 += __shfl_sync(0xffffffffu, xv, kk)     * w[kk];
            a1 += __shfl_sync(0xffffffffu, xv, kk + 1) * w[kk + 1];
            a2 += __shfl_sync(0xffffffffu, xv, kk + 2) * w[kk + 2];
            a3 += __shfl_sync(0xffffffffu, xv, kk + 3) * w[kk + 3];
        }
        red[t] = (a0 + a1) + (a2 + a3);
        __syncthreads();
        if (t < 32) {
            float s0 = red[t]       + red[t + 32];
            float s1 = red[t + 64]  + red[t + 96];
            float s2 = red[t + 128] + red[t + 160];
            float s3 = red[t + 192] + red[t + 224];
            float s4 = red[t + 256] + red[t + 288];
            float s5 = red[t + 320] + red[t + 352];
            float s6 = red[t + 384] + red[t + 416];
            float s7 = red[t + 448] + red[t + 480];
            float s  = ((s0 + s1) + (s2 + s3)) + ((s4 + s5) + (s6 + s7));
            out[g3 * 32 + t] = fmaxf(s + bias, 0.f);
        }
    }
}

// ---------------------------------------------------------------------------
extern "C" void kernel_launch(void* const* d_in, const int* in_sizes, int n_in,
                              void* d_out, int out_size)
{
    const float* state = (const float*)d_in[0];
    const int*   edges = (const int*)  d_in[1];
    const int n_edges  = in_sizes[1] / 2;

    const float* W1  = (const float*)d_in[2];
    const float* b1  = (const float*)d_in[3];
    const float* W2  = (const float*)d_in[4];
    const float* b2  = (const float*)d_in[5];
    const float* Wf1 = (const float*)d_in[6];
    const float* bf1 = (const float*)d_in[7];
    const float* Wf2 = (const float*)d_in[8];
    const float* bf2 = (const float*)d_in[9];
    const float* Wf3 = (const float*)d_in[10];
    const float* bf3 = (const float*)d_in[11];
    float* out = (float*)d_out;

    fused_net_kernel<<<NBLK, NTHREADS>>>(
        state, edges, n_edges, W1, b1, W2, b2,
        Wf1, bf1, Wf2, bf2, Wf3, bf3, out);
}